// round 17
// baseline (speedup 1.0000x reference)
#include <cuda_runtime.h>

typedef unsigned long long ull;

#define X7    (7*1048576)      // x[7] offset (floats)
#define W7OFF (7*8*4096)       // weights[7] offset (floats)
#define NBLK  592              // 148 SMs x 4 co-resident blocks (single wave)

// Scratch (device globals — no allocations allowed)
__device__ float g_uhl[8*16384*64];  // [j][b][e] 33.5MB
__device__ float g_n2[8*16384];      // [j][b]
__device__ float g_umpart[32*512];   // per-block partial sums of u over b
__device__ float g_M[4096];          // M[i,j,d] = sum_e uhm[i,j,e]*W7[j,d,e]
__device__ float g_B1[64];           // B after iteration 1
__device__ float g_t1[512];          // routing reduction 1 (re-armed in k_tail)
__device__ float g_t2[512];          // t1+t2 accumulator (zeroed by k_main)
__device__ unsigned g_bar[2];        // spin-barrier counters (zeroed by k_main)

__device__ __forceinline__ void fma2(ull &acc, ull a, ull b) {
    asm("fma.rn.f32x2 %0, %1, %2, %0;" : "+l"(acc) : "l"(a), "l"(b));
}
__device__ __forceinline__ ull pack2(float x) {
    unsigned u = __float_as_uint(x);
    ull r; asm("mov.b64 %0, {%1, %1};" : "=l"(r) : "r"(u)); return r;
}
__device__ __forceinline__ float2 unpack2(ull v) {
    unsigned lo, hi;
    asm("mov.b64 {%0, %1}, %2;" : "=r"(lo), "=r"(hi) : "l"(v));
    return make_float2(__uint_as_float(lo), __uint_as_float(hi));
}
__device__ __forceinline__ float squash_scal(float cj, float n2v) {
    float s2 = cj*cj*n2v;
    return cj*s2 / ((1.f+s2)*sqrtf(s2+1e-9f));
}
__device__ __forceinline__ int xrow(int b) {
    return (b & 31)*512 + (b >> 5);
}
__device__ __forceinline__ float dot64(const float* __restrict__ a,
                                       const float* __restrict__ b) {
    const float4* ap = (const float4*)a;
    float s = 0.f;
    #pragma unroll
    for (int k = 0; k < 16; k++) {
        float4 v = ap[k];
        s += v.x*b[4*k] + v.y*b[4*k+1] + v.z*b[4*k+2] + v.w*b[4*k+3];
    }
    return s;
}
// device-wide spin barrier; all NBLK blocks co-resident by construction.
__device__ __forceinline__ void grid_barrier(int id) {
    __syncthreads();
    if (threadIdx.x == 0) {
        __threadfence();
        atomicAdd(&g_bar[id], 1u);
        while (((volatile unsigned*)g_bar)[id] < NBLK) { }
        __threadfence();
    }
    __syncthreads();
}

// k_main: grid (256, 5) x 128 threads.
//  y<4 : GEMM slices — uhl[j,b,e], n2[j,b], t1 (c=1/8 fused routing iter 1)
//  y==4: umean partials; bx==0 also zeroes t2 + barrier counters.
__global__ __launch_bounds__(128, 6) void k_main(const float* __restrict__ x,
                                                 const float* __restrict__ w) {
    int t = threadIdx.x;             // 128

    if (blockIdx.y == 4) {           // ---- umean path ----
        __shared__ float4 red[8][16];
        int bx = blockIdx.x;
        int i = bx >> 5, sub = bx & 31;
        if (bx == 0) {
            g_t2[t] = 0.f; g_t2[t+128] = 0.f; g_t2[t+256] = 0.f; g_t2[t+384] = 0.f;
            if (t < 2) g_bar[t] = 0u;
        }
        int dq = (t & 15) * 4, g = t >> 4;     // 8 groups x 64 rows
        const float* xp = x + i*1048576 + (sub*512 + g*64)*64 + dq;
        float4 acc = make_float4(0.f,0.f,0.f,0.f);
        #pragma unroll 8
        for (int m = 0; m < 64; m++) {
            float4 v = *(const float4*)(xp + m*64);
            acc.x += v.x; acc.y += v.y; acc.z += v.z; acc.w += v.w;
        }
        red[g][t & 15] = acc;
        __syncthreads();
        if (t < 16) {
            float4 s = make_float4(0.f,0.f,0.f,0.f);
            #pragma unroll
            for (int gg = 0; gg < 8; gg++) {
                float4 v = red[gg][t];
                s.x += v.x; s.y += v.y; s.z += v.z; s.w += v.w;
            }
            *(float4*)&g_umpart[sub*512 + i*64 + t*4] = s;
        }
        return;
    }

    // ---- GEMM path ----
    __shared__ float xs[64*65];      // [d][row], stride 65
    __shared__ float ws[64*64];      // [d][col]
    __shared__ float scal_sm[2][64];
    int p0 = blockIdx.x * 64;        // b-block base
    int j0 = blockIdx.y * 2;

    {   // load + transpose 64 u-rows (gather from permuted x layout)
        int rp_ = t & 31, q = t >> 5;
        int bA = p0 + 2*rp_;
        const float* pa = x + X7 + xrow(bA)*64 + q*16;
        const float* pb = x + X7 + xrow(bA+1)*64 + q*16;
        #pragma unroll
        for (int i = 0; i < 4; i++) {
            float4 a = *(const float4*)(pa + 4*i);
            float4 b = *(const float4*)(pb + 4*i);
            int d0 = q*16 + 4*i;
            xs[(d0+0)*65 + 2*rp_] = a.x; xs[(d0+0)*65 + 2*rp_+1] = b.x;
            xs[(d0+1)*65 + 2*rp_] = a.y; xs[(d0+1)*65 + 2*rp_+1] = b.y;
            xs[(d0+2)*65 + 2*rp_] = a.z; xs[(d0+2)*65 + 2*rp_+1] = b.z;
            xs[(d0+3)*65 + 2*rp_] = a.w; xs[(d0+3)*65 + 2*rp_+1] = b.w;
        }
    }

    int cg = t & 7, rq = t >> 3;
    int r0 = rq * 4;

    #pragma unroll
    for (int jj = 0; jj < 2; jj++) {
        int j = j0 + jj;
        __syncthreads();
        {   // fill W tile (natural layout)
            const float* W7p = w + W7OFF + j*4096;
            #pragma unroll
            for (int k = 0; k < 8; k++) {
                int idx = t + 128*k;
                *(float4*)(ws + idx*4) = *(const float4*)(W7p + idx*4);
            }
        }
        __syncthreads();

        ull acc[4][4];
        #pragma unroll
        for (int r = 0; r < 4; r++)
            #pragma unroll
            for (int m = 0; m < 4; m++) acc[r][m] = 0ULL;

        #pragma unroll 8
        for (int d = 0; d < 64; d++) {
            ulonglong2 w0 = *(const ulonglong2*)&ws[d*64 + cg*4];
            ulonglong2 w1 = *(const ulonglong2*)&ws[d*64 + 32 + cg*4];
            ull xr[4];
            #pragma unroll
            for (int r = 0; r < 4; r++) xr[r] = pack2(xs[d*65 + r0 + r]);
            #pragma unroll
            for (int r = 0; r < 4; r++) {
                fma2(acc[r][0], xr[r], w0.x);
                fma2(acc[r][1], xr[r], w0.y);
                fma2(acc[r][2], xr[r], w1.x);
                fma2(acc[r][3], xr[r], w1.y);
            }
        }

        #pragma unroll
        for (int r = 0; r < 4; r++) {
            float2 v0 = unpack2(acc[r][0]), v1 = unpack2(acc[r][1]);
            float2 v2 = unpack2(acc[r][2]), v3 = unpack2(acc[r][3]);
            int row = p0 + r0 + r;
            float* base = g_uhl + j*1048576 + row*64;
            *(float4*)(base + 4*cg)      = make_float4(v0.x, v0.y, v1.x, v1.y);
            *(float4*)(base + 32 + 4*cg) = make_float4(v2.x, v2.y, v3.x, v3.y);

            float s = v0.x*v0.x + v0.y*v0.y + v1.x*v1.x + v1.y*v1.y
                    + v2.x*v2.x + v2.y*v2.y + v3.x*v3.x + v3.y*v3.y;
            #pragma unroll
            for (int off = 1; off < 8; off <<= 1)
                s += __shfl_xor_sync(~0u, s, off);
            if (cg == 0) {
                g_n2[j*16384 + row] = s;
                scal_sm[jj][r0 + r] = squash_scal(0.125f, s);
            }
        }
    }

    // Fused routing iteration 1: t1[jj][d] = sum_r scal_sm[jj][r] * x[r][d]
    __syncthreads();
    {
        int d = t & 63, jj2 = t >> 6;
        float acc = 0.f;
        #pragma unroll 16
        for (int r = 0; r < 64; r++)
            acc += scal_sm[jj2][r] * xs[d*65 + r];
        atomicAdd(&g_t1[(j0 + jj2)*64 + d], acc);
    }
}

// Persistent tail: phase1 (uhm->M->B1 on blocks 0-15; others prefetch uhl to L2)
// | barrier | phase2 (route reduction 2 on blocks 0-511; block0 folds/zeroes t1)
// | barrier | phase3 (all blocks: B2 -> c3 -> scale uhl -> out).
__global__ __launch_bounds__(256, 4) void k_tail(const float* __restrict__ x,
                                                 const float* __restrict__ w,
                                                 float* __restrict__ out) {
    __shared__ float sm[2432];
    int t = threadIdx.x, bid = blockIdx.x;

    // ---------------- phase 1 ----------------
    if (bid < 16) {
        float* um    = sm;          // 512
        float* t1s   = sm + 512;    // 512
        float* uhm_s = sm + 1024;   // 256
        float* Ms    = sm + 1280;   // 256
        #pragma unroll
        for (int o = 0; o < 2; o++) {
            int idx = t + 256*o;
            float s = 0.f;
            #pragma unroll
            for (int bx = 0; bx < 32; bx++) s += g_umpart[bx*512 + idx];
            um[idx] = s * (1.f/16384.f);
            t1s[idx] = g_t1[idx];
        }
        __syncthreads();
        int q = t >> 6, e = t & 63;
        int ij = bid*4 + q, i = ij >> 3, j = ij & 7;
        {
            const float* wp = w + ij*4096 + e;
            const float* up = um + i*64;
            float s = 0.f;
            #pragma unroll 8
            for (int d = 0; d < 64; d++) s += wp[d*64] * up[d];
            uhm_s[q*64 + e] = s;
        }
        __syncthreads();
        {
            float mval = dot64(w + W7OFF + j*4096 + e*64, uhm_s + q*64);
            g_M[ij*64 + e] = mval;
            Ms[q*64 + e] = mval;
        }
        __syncthreads();
        if (t < 4) {
            int ij2 = bid*4 + t, j2 = ij2 & 7;
            g_B1[ij2] = dot64(Ms + t*64, t1s + j2*64) * (1.f/16384.f);
        }
    } else {
        // warm L2 with uhl (33.5MB = 262144 lines of 128B) while uhm runs
        const char* base = (const char*)g_uhl;
        int gp = (bid - 16)*256 + t;         // 0..147455
        #pragma unroll
        for (int k = 0; k < 2; k++) {
            int l = gp + k*147456;
            if (l < 262144)
                asm volatile("prefetch.global.L2 [%0];" :: "l"(base + (size_t)l*128));
        }
    }
    grid_barrier(0);

    // ---------------- phase 2 ----------------
    if (bid == 0) {
        atomicAdd(&g_t2[t],     g_t1[t]);
        atomicAdd(&g_t2[t+256], g_t1[t+256]);
        g_t1[t] = 0.f; g_t1[t+256] = 0.f;    // re-arm for next replay
    }
    if (bid < 512) {
        float* red    = sm;          // 4x512
        float* scal_s = sm + 2048;   // 256
        float* Bsm    = sm + 2304;   // 64
        float* c_s    = sm + 2368;   // 8
        int p0 = bid * 32;
        int d = t & 63, g = t >> 6;
        if (t < 64) Bsm[t] = g_B1[t];
        __syncthreads();
        if (t < 8) {
            float m = Bsm[t];
            #pragma unroll
            for (int i = 1; i < 8; i++) m = fmaxf(m, Bsm[i*8+t]);
            float sum = 0.f, e7 = 0.f;
            #pragma unroll
            for (int i = 0; i < 8; i++) {
                float e = expf(Bsm[i*8+t] - m);
                sum += e; if (i == 7) e7 = e;
            }
            c_s[t] = e7/sum;
        }
        __syncthreads();
        {   int r = t >> 3, j = t & 7;
            scal_s[t] = squash_scal(c_s[j], g_n2[j*16384 + p0 + r]); }
        __syncthreads();
        const float* xb = x + X7 + d;
        float xv[8];
        #pragma unroll
        for (int m = 0; m < 8; m++)
            xv[m] = xb[xrow(p0 + g*8 + m)*64];
        float acc[8] = {0,0,0,0,0,0,0,0};
        #pragma unroll
        for (int m = 0; m < 8; m++) {
            int r = g*8 + m;
            #pragma unroll
            for (int j = 0; j < 8; j++) acc[j] += scal_s[r*8+j] * xv[m];
        }
        #pragma unroll
        for (int j = 0; j < 8; j++) red[g*512 + j*64 + d] = acc[j];
        __syncthreads();
        #pragma unroll
        for (int o = 0; o < 2; o++) {
            int idx = t + 256*o;
            atomicAdd(&g_t2[idx],
                      red[idx] + red[512+idx] + red[1024+idx] + red[1536+idx]);
        }
    }
    grid_barrier(1);

    // ---------------- phase 3 ----------------
    {
        float* t2s   = sm;          // 512
        float* B2    = sm + 512;    // 64
        float* c3s   = sm + 576;    // 8
        float* scal3 = sm + 640;    // 128
        t2s[t] = g_t2[t]; t2s[t+256] = g_t2[t+256];
        __syncthreads();
        if (t < 64)
            B2[t] = dot64(g_M + t*64, t2s + (t & 7)*64) * (1.f/16384.f);
        __syncthreads();
        if (t < 8) {
            float m = B2[t];
            #pragma unroll
            for (int i = 1; i < 8; i++) m = fmaxf(m, B2[i*8+t]);
            float sum = 0.f, e7 = 0.f;
            #pragma unroll
            for (int i = 0; i < 8; i++) {
                float e = expf(B2[i*8+t] - m);
                sum += e; if (i == 7) e7 = e;
            }
            c3s[t] = e7/sum;
        }
        __syncthreads();
        for (int tile = bid; tile < 1024; tile += NBLK) {
            int j = tile >> 7, p0 = (tile & 127) * 128;
            if (t < 128) scal3[t] = squash_scal(c3s[j], g_n2[j*16384 + p0 + t]);
            __syncthreads();
            const float4* src = (const float4*)(g_uhl + j*1048576 + p0*64);
            float4* dst = (float4*)(out + j*1048576 + p0*64);
            #pragma unroll
            for (int k = 0; k < 8; k++) {
                int idx = k*256 + t;       // 2048 float4
                float4 v = src[idx];
                float s = scal3[idx >> 4];
                v.x *= s; v.y *= s; v.z *= s; v.w *= s;
                dst[idx] = v;
            }
            __syncthreads();
        }
    }
}

extern "C" void kernel_launch(void* const* d_in, const int* in_sizes, int n_in,
                              void* d_out, int out_size) {
    const float* x = (const float*)d_in[0];
    const float* w = (const float*)d_in[1];
    float* out = (float*)d_out;
    k_main<<<dim3(256, 5), 128>>>(x, w);   // gemm(uhl,n2,t1) + umean; zero t2+bars
    k_tail<<<NBLK, 256>>>(x, w, out);      // uhm|route2|out with device barriers
}